// round 1
// baseline (speedup 1.0000x reference)
#include <cuda_runtime.h>
#include <cstddef>

#define D_MODEL 1024
#define NHEAD   16
#define HDIM    64
#define BATCH   4
#define SEQ     2048
#define NTOK    (BATCH*SEQ)   // 8192

// Scratch (no allocations allowed): 4 x 32 MB
__device__ float g_Q[(size_t)BATCH*NHEAD*SEQ*HDIM];
__device__ float g_K[(size_t)BATCH*NHEAD*SEQ*HDIM];
__device__ float g_V[(size_t)BATCH*NHEAD*SEQ*HDIM];
__device__ float g_X[(size_t)NTOK*D_MODEL];

// ---------------------------------------------------------------------------
// GEMM: Y[n][j] = sum_k A[n][k] * W[j][k] + bias[j]
// MODE 0: scatter into [B,H,S,HD] layout (QKV projections)
// MODE 1: plain [NTOK, D_MODEL] (output projection)
// 128x128 block tile, BK=16, 256 threads, 8x8 per-thread microtile.
// ---------------------------------------------------------------------------
template<int MODE>
__global__ void __launch_bounds__(256)
gemm_bias_kernel(const float* __restrict__ A, const float* __restrict__ W,
                 const float* __restrict__ bias, float* __restrict__ Y)
{
    __shared__ float As[16][132];   // [k][row], pad 4 to break store conflicts
    __shared__ float Bs[16][132];   // [k][col]

    const int t  = threadIdx.x;
    const int tr = t >> 4;          // 0..15  (row group)
    const int tc = t & 15;          // 0..15  (col group)
    const int n0 = blockIdx.y * 128;
    const int j0 = blockIdx.x * 128;

    const float* Ap = A + (size_t)n0 * D_MODEL;
    const float* Wp = W + (size_t)j0 * D_MODEL;

    float acc[8][8];
    #pragma unroll
    for (int i = 0; i < 8; i++)
        #pragma unroll
        for (int j = 0; j < 8; j++) acc[i][j] = 0.f;

    const int lrow = t >> 2;        // 0..63
    const int lk4  = t & 3;         // 0..3  (float4 index within 16-wide k slab)

    for (int k0 = 0; k0 < D_MODEL; k0 += 16) {
        #pragma unroll
        for (int p = 0; p < 2; p++) {
            const int row = lrow + p * 64;
            float4 a = *reinterpret_cast<const float4*>(Ap + (size_t)row * D_MODEL + k0 + lk4 * 4);
            As[lk4*4+0][row] = a.x;
            As[lk4*4+1][row] = a.y;
            As[lk4*4+2][row] = a.z;
            As[lk4*4+3][row] = a.w;
            float4 b = *reinterpret_cast<const float4*>(Wp + (size_t)row * D_MODEL + k0 + lk4 * 4);
            Bs[lk4*4+0][row] = b.x;
            Bs[lk4*4+1][row] = b.y;
            Bs[lk4*4+2][row] = b.z;
            Bs[lk4*4+3][row] = b.w;
        }
        __syncthreads();

        #pragma unroll
        for (int kk = 0; kk < 16; kk++) {
            float4 a0 = *reinterpret_cast<const float4*>(&As[kk][tr*8]);
            float4 a1 = *reinterpret_cast<const float4*>(&As[kk][tr*8+4]);
            float4 b0 = *reinterpret_cast<const float4*>(&Bs[kk][tc*8]);
            float4 b1 = *reinterpret_cast<const float4*>(&Bs[kk][tc*8+4]);
            float af[8] = {a0.x,a0.y,a0.z,a0.w,a1.x,a1.y,a1.z,a1.w};
            float bf[8] = {b0.x,b0.y,b0.z,b0.w,b1.x,b1.y,b1.z,b1.w};
            #pragma unroll
            for (int i = 0; i < 8; i++)
                #pragma unroll
                for (int j = 0; j < 8; j++)
                    acc[i][j] += af[i] * bf[j];
        }
        __syncthreads();
    }

    #pragma unroll
    for (int i = 0; i < 8; i++) {
        const int n = n0 + tr*8 + i;
        #pragma unroll
        for (int jv = 0; jv < 2; jv++) {
            const int jj = j0 + tc*8 + jv*4;
            float4 y;
            y.x = acc[i][jv*4+0] + bias[jj+0];
            y.y = acc[i][jv*4+1] + bias[jj+1];
            y.z = acc[i][jv*4+2] + bias[jj+2];
            y.w = acc[i][jv*4+3] + bias[jj+3];
            if (MODE == 0) {
                const int bb = n / SEQ, s = n % SEQ;
                const int h = jj / HDIM, hd = jj % HDIM;  // 4-elem group never crosses a head
                *reinterpret_cast<float4*>(Y + (((size_t)(bb*NHEAD + h))*SEQ + s)*HDIM + hd) = y;
            } else {
                *reinterpret_cast<float4*>(Y + (size_t)n * D_MODEL + jj) = y;
            }
        }
    }
}

// ---------------------------------------------------------------------------
// Flash attention, fp32. One block = one (b,h) x 64-query tile.
// 256 threads; each thread owns a 4x4 output microtile. Online softmax with
// width-16 shuffle reductions. P^T is written over the K^T smem buffer
// (scores are fully in registers before the overwrite).
// ---------------------------------------------------------------------------
#define AT_STR 68   // smem row stride (floats): 16B-aligned, conflict-benign
#define SMEM_ATTN (3*64*AT_STR*(int)sizeof(float))   // 52,224 B

__global__ void __launch_bounds__(256)
attn_kernel()
{
    extern __shared__ float sm[];
    float* Qt  = sm;               // [64][AT_STR]  Q^T: Qt[d][i]
    float* KPt = sm + 64*AT_STR;   // K^T during scores, then P^T: [d|k][col|i]
    float* Vs  = sm + 2*64*AT_STR; // [k][j]

    const int t  = threadIdx.x;
    const int tr = t >> 4;         // 0..15 -> rows tr*4..tr*4+3
    const int tc = t & 15;         // 0..15 -> cols tc*4..tc*4+3
    const int bh = blockIdx.y;
    const int b  = bh >> 4;
    const int h  = bh & 15;
    const int q0 = blockIdx.x * 64;

    const float* Qg = g_Q + ((size_t)bh * SEQ + q0) * HDIM;
    const float* Kg = g_K + (size_t)bh * SEQ * HDIM;
    const float* Vg = g_V + (size_t)bh * SEQ * HDIM;

    // Load Q tile transposed (once)
    #pragma unroll
    for (int p = 0; p < 4; p++) {
        const int v   = t + p*256;    // float4 index 0..1023
        const int row = v >> 4;       // 0..63
        const int d4  = v & 15;       // 0..15
        float4 q = *reinterpret_cast<const float4*>(Qg + (size_t)row*HDIM + d4*4);
        Qt[(d4*4+0)*AT_STR + row] = q.x;
        Qt[(d4*4+1)*AT_STR + row] = q.y;
        Qt[(d4*4+2)*AT_STR + row] = q.z;
        Qt[(d4*4+3)*AT_STR + row] = q.w;
    }

    float acc[4][4];
    float m_i[4], l_i[4];
    #pragma unroll
    for (int i = 0; i < 4; i++) {
        m_i[i] = -1e30f; l_i[i] = 0.f;
        #pragma unroll
        for (int j = 0; j < 4; j++) acc[i][j] = 0.f;
    }
    __syncthreads();

    for (int kt = 0; kt < SEQ; kt += 64) {
        // Load K^T and V tiles
        #pragma unroll
        for (int p = 0; p < 4; p++) {
            const int v   = t + p*256;
            const int row = v >> 4;
            const int d4  = v & 15;
            float4 kk4 = *reinterpret_cast<const float4*>(Kg + (size_t)(kt+row)*HDIM + d4*4);
            KPt[(d4*4+0)*AT_STR + row] = kk4.x;
            KPt[(d4*4+1)*AT_STR + row] = kk4.y;
            KPt[(d4*4+2)*AT_STR + row] = kk4.z;
            KPt[(d4*4+3)*AT_STR + row] = kk4.w;
            float4 vv = *reinterpret_cast<const float4*>(Vg + (size_t)(kt+row)*HDIM + d4*4);
            *reinterpret_cast<float4*>(&Vs[row*AT_STR + d4*4]) = vv;
        }
        __syncthreads();

        // S = Q K^T (registers)
        float sc[4][4];
        #pragma unroll
        for (int i = 0; i < 4; i++)
            #pragma unroll
            for (int j = 0; j < 4; j++) sc[i][j] = 0.f;

        #pragma unroll 16
        for (int kk = 0; kk < HDIM; kk++) {
            float4 qf = *reinterpret_cast<const float4*>(&Qt [kk*AT_STR + tr*4]);
            float4 kf = *reinterpret_cast<const float4*>(&KPt[kk*AT_STR + tc*4]);
            float qa[4] = {qf.x,qf.y,qf.z,qf.w};
            float ka[4] = {kf.x,kf.y,kf.z,kf.w};
            #pragma unroll
            for (int i = 0; i < 4; i++)
                #pragma unroll
                for (int j = 0; j < 4; j++)
                    sc[i][j] += qa[i] * ka[j];
        }
        __syncthreads();   // all K^T reads done; KPt can be reused for P^T

        // Online softmax (scale = 1/sqrt(D_MODEL) = 1/32, per reference)
        #pragma unroll
        for (int i = 0; i < 4; i++) {
            float mt = -1e30f;
            #pragma unroll
            for (int j = 0; j < 4; j++) {
                sc[i][j] *= 0.03125f;
                mt = fmaxf(mt, sc[i][j]);
            }
            mt = fmaxf(mt, __shfl_xor_sync(0xffffffffu, mt, 1, 16));
            mt = fmaxf(mt, __shfl_xor_sync(0xffffffffu, mt, 2, 16));
            mt = fmaxf(mt, __shfl_xor_sync(0xffffffffu, mt, 4, 16));
            mt = fmaxf(mt, __shfl_xor_sync(0xffffffffu, mt, 8, 16));

            const float mnew = fmaxf(m_i[i], mt);
            const float corr = __expf(m_i[i] - mnew);
            m_i[i] = mnew;

            float rs = 0.f;
            #pragma unroll
            for (int j = 0; j < 4; j++) {
                const float pv = __expf(sc[i][j] - mnew);
                sc[i][j] = pv;
                rs += pv;
            }
            rs += __shfl_xor_sync(0xffffffffu, rs, 1, 16);
            rs += __shfl_xor_sync(0xffffffffu, rs, 2, 16);
            rs += __shfl_xor_sync(0xffffffffu, rs, 4, 16);
            rs += __shfl_xor_sync(0xffffffffu, rs, 8, 16);

            l_i[i] = l_i[i]*corr + rs;
            #pragma unroll
            for (int j = 0; j < 4; j++) acc[i][j] *= corr;
        }

        // Write P^T over KPt: P^T[k][i] at KPt[(tc*4+j)*AT_STR + tr*4 + i]
        #pragma unroll
        for (int j = 0; j < 4; j++) {
            float4 pv = make_float4(sc[0][j], sc[1][j], sc[2][j], sc[3][j]);
            *reinterpret_cast<float4*>(&KPt[(tc*4+j)*AT_STR + tr*4]) = pv;
        }
        __syncthreads();

        // acc += P V
        #pragma unroll 16
        for (int kk = 0; kk < 64; kk++) {
            float4 pf = *reinterpret_cast<const float4*>(&KPt[kk*AT_STR + tr*4]);
            float4 vf = *reinterpret_cast<const float4*>(&Vs [kk*AT_STR + tc*4]);
            float pa[4] = {pf.x,pf.y,pf.z,pf.w};
            float va[4] = {vf.x,vf.y,vf.z,vf.w};
            #pragma unroll
            for (int i = 0; i < 4; i++)
                #pragma unroll
                for (int j = 0; j < 4; j++)
                    acc[i][j] += pa[i] * va[j];
        }
        __syncthreads();   // before next tile overwrites KPt / Vs
    }

    // Epilogue: normalize and write to [B,S,D] scratch (head-interleaved)
    #pragma unroll
    for (int i = 0; i < 4; i++) {
        const float inv = 1.f / l_i[i];
        const int row = q0 + tr*4 + i;
        float4 y = make_float4(acc[i][0]*inv, acc[i][1]*inv, acc[i][2]*inv, acc[i][3]*inv);
        *reinterpret_cast<float4*>(&g_X[((size_t)b*SEQ + row)*D_MODEL + h*HDIM + tc*4]) = y;
    }
}

// ---------------------------------------------------------------------------
extern "C" void kernel_launch(void* const* d_in, const int* in_sizes, int n_in,
                              void* d_out, int out_size)
{
    (void)in_sizes; (void)n_in; (void)out_size;
    const float* q  = (const float*)d_in[0];
    const float* k  = (const float*)d_in[1];
    const float* v  = (const float*)d_in[2];
    const float* Wq = (const float*)d_in[3];
    const float* bq = (const float*)d_in[4];
    const float* Wk = (const float*)d_in[5];
    const float* bk = (const float*)d_in[6];
    const float* Wv = (const float*)d_in[7];
    const float* bv = (const float*)d_in[8];
    const float* Wo = (const float*)d_in[9];
    const float* bo = (const float*)d_in[10];
    float* out = (float*)d_out;

    float *gq, *gk, *gv, *gx;
    cudaGetSymbolAddress((void**)&gq, g_Q);
    cudaGetSymbolAddress((void**)&gk, g_K);
    cudaGetSymbolAddress((void**)&gv, g_V);
    cudaGetSymbolAddress((void**)&gx, g_X);

    cudaFuncSetAttribute(attn_kernel,
                         cudaFuncAttributeMaxDynamicSharedMemorySize, SMEM_ATTN);

    const dim3 gg(D_MODEL/128, NTOK/128);   // (8, 64)
    const dim3 gb(256);

    gemm_bias_kernel<0><<<gg, gb>>>(q, Wq, bq, gq);
    gemm_bias_kernel<0><<<gg, gb>>>(k, Wk, bk, gk);
    gemm_bias_kernel<0><<<gg, gb>>>(v, Wv, bv, gv);

    attn_kernel<<<dim3(SEQ/64, BATCH*NHEAD), 256, SMEM_ATTN>>>();

    gemm_bias_kernel<1><<<gg, gb>>>(gx, Wo, bo, out);
}

// round 8
// speedup vs baseline: 2.1609x; 2.1609x over previous
#include <cuda_runtime.h>
#include <cuda_bf16.h>
#include <cstdint>
#include <cstddef>

#define D_MODEL 1024
#define NHEAD   16
#define HDIM    64
#define BATCH   4
#define SEQ     2048
#define NTOK    (BATCH*SEQ)   // 8192

// Scratch (no allocations allowed)
__device__ float g_Q[(size_t)BATCH*NHEAD*SEQ*HDIM];
__device__ float g_K[(size_t)BATCH*NHEAD*SEQ*HDIM];
__device__ float g_V[(size_t)BATCH*NHEAD*SEQ*HDIM];
__device__ float g_X[(size_t)NTOK*D_MODEL];

// ---------------------------------------------------------------------------
// Helpers
// ---------------------------------------------------------------------------
__device__ __forceinline__ uint32_t smem_u32(const void* p) {
    uint32_t a;
    asm("{ .reg .u64 t; cvta.to.shared.u64 t, %1; cvt.u32.u64 %0, t; }"
        : "=r"(a) : "l"(p));
    return a;
}

// D(f32) += A(bf16 m16k16 row) * B(bf16 k16n8 col)   [legacy HMMA, sm_80+]
__device__ __forceinline__ void mma16816(float* d, const uint32_t* a, const uint32_t* b) {
    asm volatile(
        "mma.sync.aligned.m16n8k16.row.col.f32.bf16.bf16.f32 "
        "{%0,%1,%2,%3}, {%4,%5,%6,%7}, {%8,%9}, {%0,%1,%2,%3};"
        : "+f"(d[0]), "+f"(d[1]), "+f"(d[2]), "+f"(d[3])
        : "r"(a[0]), "r"(a[1]), "r"(a[2]), "r"(a[3]), "r"(b[0]), "r"(b[1]));
}

// transposed 8x8 b16 ldmatrix x2 (for V as B-operand from key-major smem)
__device__ __forceinline__ void ldsm_x2_trans(uint32_t& r0, uint32_t& r1, uint32_t saddr) {
    asm volatile("ldmatrix.sync.aligned.m8n8.x2.trans.shared.b16 {%0,%1}, [%2];"
                 : "=r"(r0), "=r"(r1) : "r"(saddr));
}

// split two fp32 into packed bf16x2 hi and lo
__device__ __forceinline__ void split2(float x, float y, uint32_t& hi, uint32_t& lo) {
    __nv_bfloat162 h, l;
    h.x = __float2bfloat16(x);
    h.y = __float2bfloat16(y);
    l.x = __float2bfloat16(x - __bfloat162float(h.x));
    l.y = __float2bfloat16(y - __bfloat162float(h.y));
    hi = *reinterpret_cast<uint32_t*>(&h);
    lo = *reinterpret_cast<uint32_t*>(&l);
}

// exp on the FMA pipe (no MUFU — MUFU is the 1.9ms floor at 268M softmax exps).
// round-to-int magic + degree-5 2^f Taylor + exponent-bit inject. rel err ~2e-6.
__device__ __forceinline__ float fexp(float x) {
    x = fmaxf(x, -87.0f);
    const float L2E = 1.4426950408889634f;
    float t = fmaf(x, L2E, 12582912.0f);      // 1.5*2^23 round-to-nearest-int trick
    float n = t - 12582912.0f;
    float f = fmaf(x, L2E, -n);               // f in [-0.5, 0.5]
    float p = 1.3333558e-3f;
    p = fmaf(p, f, 9.6181291e-3f);
    p = fmaf(p, f, 5.5504109e-2f);
    p = fmaf(p, f, 2.4022651e-1f);
    p = fmaf(p, f, 6.9314718e-1f);
    p = fmaf(p, f, 1.0f);
    int e = (int)n;
    return p * __int_as_float((e + 127) << 23);
}

// ---------------------------------------------------------------------------
// Split-bf16 tensor-core GEMM (proven mapping): Y = A*W^T + bias
// ---------------------------------------------------------------------------
#define BKF 32
#define STR 40          // GEMM smem row stride in bf16 (32 cols used; conflict-free)

template<int MODE>
__global__ void __launch_bounds__(256)
gemm_tc(const float* __restrict__ A, const float* __restrict__ W,
        const float* __restrict__ bias, float* __restrict__ Y)
{
    __shared__ __nv_bfloat16 sA[2][128*STR];
    __shared__ __nv_bfloat16 sB[2][128*STR];

    const int t    = threadIdx.x;
    const int wid  = t >> 5;
    const int lane = t & 31;
    const int grp  = lane >> 2;
    const int qid  = lane & 3;
    const int wm   = wid & 3;
    const int wn   = wid >> 2;
    const int n0   = blockIdx.y * 128;
    const int j0   = blockIdx.x * 128;

    const int crow = t >> 1;
    const int cc0  = (t & 1) * 16;

    float acc[2][8][4];
    #pragma unroll
    for (int i = 0; i < 2; i++)
        #pragma unroll
        for (int j = 0; j < 8; j++)
            #pragma unroll
            for (int c = 0; c < 4; c++) acc[i][j][c] = 0.f;

    float4 av[4], bv[4];
    #pragma unroll
    for (int p = 0; p < 4; p++) {
        av[p] = *reinterpret_cast<const float4*>(A + (size_t)(n0+crow)*D_MODEL + cc0 + p*4);
        bv[p] = *reinterpret_cast<const float4*>(W + (size_t)(j0+crow)*D_MODEL + cc0 + p*4);
    }

    const int NIT = D_MODEL / BKF;
    for (int it = 0; it < NIT; it++) {
        __syncthreads();

        #pragma unroll
        for (int p = 0; p < 4; p++) {
            const int kc = cc0 + p*4;
            uint32_t h0, l0, h1, l1;
            split2(av[p].x, av[p].y, h0, l0);
            split2(av[p].z, av[p].w, h1, l1);
            *reinterpret_cast<uint32_t*>(&sA[0][crow*STR + kc])     = h0;
            *reinterpret_cast<uint32_t*>(&sA[0][crow*STR + kc + 2]) = h1;
            *reinterpret_cast<uint32_t*>(&sA[1][crow*STR + kc])     = l0;
            *reinterpret_cast<uint32_t*>(&sA[1][crow*STR + kc + 2]) = l1;
            split2(bv[p].x, bv[p].y, h0, l0);
            split2(bv[p].z, bv[p].w, h1, l1);
            *reinterpret_cast<uint32_t*>(&sB[0][crow*STR + kc])     = h0;
            *reinterpret_cast<uint32_t*>(&sB[0][crow*STR + kc + 2]) = h1;
            *reinterpret_cast<uint32_t*>(&sB[1][crow*STR + kc])     = l0;
            *reinterpret_cast<uint32_t*>(&sB[1][crow*STR + kc + 2]) = l1;
        }
        __syncthreads();

        if (it + 1 < NIT) {
            const int kb = (it + 1) * BKF;
            #pragma unroll
            for (int p = 0; p < 4; p++) {
                av[p] = *reinterpret_cast<const float4*>(A + (size_t)(n0+crow)*D_MODEL + kb + cc0 + p*4);
                bv[p] = *reinterpret_cast<const float4*>(W + (size_t)(j0+crow)*D_MODEL + kb + cc0 + p*4);
            }
        }

        #pragma unroll
        for (int ks = 0; ks < 2; ks++) {
            const int kb = ks*16 + qid*2;

            uint32_t af[2][2][4];
            #pragma unroll
            for (int im = 0; im < 2; im++) {
                const int r = wm*32 + im*16 + grp;
                #pragma unroll
                for (int h = 0; h < 2; h++) {
                    af[im][h][0] = *reinterpret_cast<const uint32_t*>(&sA[h][(r  )*STR + kb    ]);
                    af[im][h][1] = *reinterpret_cast<const uint32_t*>(&sA[h][(r+8)*STR + kb    ]);
                    af[im][h][2] = *reinterpret_cast<const uint32_t*>(&sA[h][(r  )*STR + kb + 8]);
                    af[im][h][3] = *reinterpret_cast<const uint32_t*>(&sA[h][(r+8)*STR + kb + 8]);
                }
            }

            #pragma unroll
            for (int in_ = 0; in_ < 8; in_++) {
                const int nr = wn*64 + in_*8 + grp;
                uint32_t bh[2], bl[2];
                bh[0] = *reinterpret_cast<const uint32_t*>(&sB[0][nr*STR + kb    ]);
                bh[1] = *reinterpret_cast<const uint32_t*>(&sB[0][nr*STR + kb + 8]);
                bl[0] = *reinterpret_cast<const uint32_t*>(&sB[1][nr*STR + kb    ]);
                bl[1] = *reinterpret_cast<const uint32_t*>(&sB[1][nr*STR + kb + 8]);
                #pragma unroll
                for (int im = 0; im < 2; im++) {
                    mma16816(acc[im][in_], af[im][0], bh);
                    mma16816(acc[im][in_], af[im][0], bl);
                    mma16816(acc[im][in_], af[im][1], bh);
                }
            }
        }
    }

    #pragma unroll
    for (int im = 0; im < 2; im++) {
        #pragma unroll
        for (int in_ = 0; in_ < 8; in_++) {
            const int gc = j0 + wn*64 + in_*8 + qid*2;
            const float2 bi = *reinterpret_cast<const float2*>(bias + gc);
            #pragma unroll
            for (int half = 0; half < 2; half++) {
                const int gr = n0 + wm*32 + im*16 + grp + half*8;
                float2 y;
                y.x = acc[im][in_][half*2 + 0] + bi.x;
                y.y = acc[im][in_][half*2 + 1] + bi.y;
                if (MODE == 0) {
                    const int bb = gr / SEQ, s_ = gr % SEQ;
                    const int h  = gc / HDIM, hd = gc % HDIM;
                    *reinterpret_cast<float2*>(
                        Y + (((size_t)(bb*NHEAD + h))*SEQ + s_)*HDIM + hd) = y;
                } else {
                    *reinterpret_cast<float2*>(Y + (size_t)gr * D_MODEL + gc) = y;
                }
            }
        }
    }
}

// ---------------------------------------------------------------------------
// Flash attention on mma.sync, split-bf16 everywhere, polynomial exp.
// ATS=72 row stride (>=64 cols; was the R7 IMA: STR=40 < 64-col tiles).
// ---------------------------------------------------------------------------
#define ATS 72          // attention smem row stride in bf16 (144B rows)

__global__ void __launch_bounds__(256, 2)
attn_mma()
{
    __shared__ __align__(16) __nv_bfloat16 sKh[64*ATS], sKl[64*ATS];
    __shared__ __align__(16) __nv_bfloat16 sVh[64*ATS], sVl[64*ATS];

    const int t    = threadIdx.x;
    const int wid  = t >> 5;
    const int lane = t & 31;
    const int grp  = lane >> 2;
    const int qid  = lane & 3;
    const int bh   = blockIdx.y;
    const int b    = bh >> 4;
    const int h    = bh & 15;
    const int q0   = blockIdx.x * 128;

    const float* Qg = g_Q + ((size_t)bh*SEQ + q0 + wid*16) * HDIM;
    const float* Kg = g_K + (size_t)bh*SEQ*HDIM;
    const float* Vg = g_V + (size_t)bh*SEQ*HDIM;

    const uint32_t sVh_u = smem_u32(sVh);
    const uint32_t sVl_u = smem_u32(sVl);

    // Q fragments (scaled by 1/32 = 1/sqrt(D_MODEL)), split hi/lo, kept in regs
    uint32_t qh[4][4], ql[4][4];
    #pragma unroll
    for (int ks = 0; ks < 4; ks++) {
        #pragma unroll
        for (int j = 0; j < 4; j++) {
            const int r = grp + (j & 1) * 8;          // a0,a2: row grp; a1,a3: grp+8
            const int c = ks*16 + qid*2 + (j >> 1)*8; // a0,a1: k+0; a2,a3: k+8
            float2 v = *reinterpret_cast<const float2*>(Qg + r*HDIM + c);
            split2(v.x * 0.03125f, v.y * 0.03125f, qh[ks][j], ql[ks][j]);
        }
    }

    float acc[8][4];
    #pragma unroll
    for (int j = 0; j < 8; j++)
        #pragma unroll
        for (int c = 0; c < 4; c++) acc[j][c] = 0.f;
    float m0 = -1e30f, m1 = -1e30f, l0 = 0.f, l1 = 0.f;

    for (int kt = 0; kt < SEQ/64; kt++) {
        const float* Kt = Kg + (size_t)kt*64*HDIM;
        const float* Vt = Vg + (size_t)kt*64*HDIM;

        __syncthreads();
        // convert K,V tiles (64 keys x 64 dims) to split bf16 smem
        #pragma unroll
        for (int p = 0; p < 4; p++) {
            const int i   = t + p*256;      // 0..1023
            const int row = i >> 4;
            const int c4  = i & 15;
            float4 kv = *reinterpret_cast<const float4*>(Kt + row*HDIM + c4*4);
            uint32_t h0, lo0, h1, lo1;
            split2(kv.x, kv.y, h0, lo0);
            split2(kv.z, kv.w, h1, lo1);
            *reinterpret_cast<uint32_t*>(&sKh[row*ATS + c4*4])     = h0;
            *reinterpret_cast<uint32_t*>(&sKh[row*ATS + c4*4 + 2]) = h1;
            *reinterpret_cast<uint32_t*>(&sKl[row*ATS + c4*4])     = lo0;
            *reinterpret_cast<uint32_t*>(&sKl[row*ATS + c4*4 + 2]) = lo1;
            float4 vv = *reinterpret_cast<const float4*>(Vt + row*HDIM + c4*4);
            split2(vv.x, vv.y, h0, lo0);
            split2(vv.z, vv.w, h1, lo1);
            *reinterpret_cast<uint32_t*>(&sVh[row*ATS + c4*4])     = h0;
            *reinterpret_cast<uint32_t*>(&sVh[row*ATS + c4*4 + 2]) = h1;
            *reinterpret_cast<uint32_t*>(&sVl[row*ATS + c4*4])     = lo0;
            *reinterpret_cast<uint32_t*>(&sVl[row*ATS + c4*4 + 2]) = lo1;
        }
        __syncthreads();

        // S = Q K^T : 8 n8-tiles of keys, 4 k16 steps over dims
        float sc[8][4];
        #pragma unroll
        for (int j = 0; j < 8; j++)
            #pragma unroll
            for (int c = 0; c < 4; c++) sc[j][c] = 0.f;

        #pragma unroll
        for (int ks = 0; ks < 4; ks++) {
            #pragma unroll
            for (int in_ = 0; in_ < 8; in_++) {
                const int nr = in_*8 + grp;          // key index
                const int kb = ks*16 + qid*2;        // dim index
                uint32_t bh2[2], bl2[2];
                bh2[0] = *reinterpret_cast<const uint32_t*>(&sKh[nr*ATS + kb    ]);
                bh2[1] = *reinterpret_cast<const uint32_t*>(&sKh[nr*ATS + kb + 8]);
                bl2[0] = *reinterpret_cast<const uint32_t*>(&sKl[nr*ATS + kb    ]);
                bl2[1] = *reinterpret_cast<const uint32_t*>(&sKl[nr*ATS + kb + 8]);
                mma16816(sc[in_], qh[ks], bh2);
                mma16816(sc[in_], qh[ks], bl2);
                mma16816(sc[in_], ql[ks], bh2);
            }
        }

        // online softmax: row0 = grp (c0,c1), row1 = grp+8 (c2,c3)
        {
            float mt0 = -1e30f, mt1 = -1e30f;
            #pragma unroll
            for (int j = 0; j < 8; j++) {
                mt0 = fmaxf(mt0, fmaxf(sc[j][0], sc[j][1]));
                mt1 = fmaxf(mt1, fmaxf(sc[j][2], sc[j][3]));
            }
            mt0 = fmaxf(mt0, __shfl_xor_sync(0xffffffffu, mt0, 1));
            mt0 = fmaxf(mt0, __shfl_xor_sync(0xffffffffu, mt0, 2));
            mt1 = fmaxf(mt1, __shfl_xor_sync(0xffffffffu, mt1, 1));
            mt1 = fmaxf(mt1, __shfl_xor_sync(0xffffffffu, mt1, 2));

            const float mn0 = fmaxf(m0, mt0);
            const float mn1 = fmaxf(m1, mt1);
            const float co0 = fexp(m0 - mn0);
            const float co1 = fexp(m1 - mn1);
            m0 = mn0; m1 = mn1;

            float rs0 = 0.f, rs1 = 0.f;
            #pragma unroll
            for (int j = 0; j < 8; j++) {
                sc[j][0] = fexp(sc[j][0] - mn0);
                sc[j][1] = fexp(sc[j][1] - mn0);
                sc[j][2] = fexp(sc[j][2] - mn1);
                sc[j][3] = fexp(sc[j][3] - mn1);
                rs0 += sc[j][0] + sc[j][1];
                rs1 += sc[j][2] + sc[j][3];
            }
            rs0 += __shfl_xor_sync(0xffffffffu, rs0, 1);
            rs0 += __shfl_xor_sync(0xffffffffu, rs0, 2);
            rs1 += __shfl_xor_sync(0xffffffffu, rs1, 1);
            rs1 += __shfl_xor_sync(0xffffffffu, rs1, 2);
            l0 = l0*co0 + rs0;
            l1 = l1*co1 + rs1;

            #pragma unroll
            for (int j = 0; j < 8; j++) {
                acc[j][0] *= co0; acc[j][1] *= co0;
                acc[j][2] *= co1; acc[j][3] *= co1;
            }
        }

        // O += P V : k-dim = 64 keys (4 k16 steps), n = 64 dims (8 n8 tiles)
        #pragma unroll
        for (int ks = 0; ks < 4; ks++) {
            // P A-fragments from the exp'd score fragments (n8-tile pair 2ks, 2ks+1)
            uint32_t ah[4], al[4];
            split2(sc[2*ks  ][0], sc[2*ks  ][1], ah[0], al[0]);
            split2(sc[2*ks  ][2], sc[2*ks  ][3], ah[1], al[1]);
            split2(sc[2*ks+1][0], sc[2*ks+1][1], ah[2], al[2]);
            split2(sc[2*ks+1][2], sc[2*ks+1][3], ah[3], al[3]);

            const uint32_t roff = (uint32_t)((ks*16 + (lane & 15))*ATS) * 2u;
            #pragma unroll
            for (int in2 = 0; in2 < 8; in2++) {
                uint32_t bhf[2], blf[2];
                ldsm_x2_trans(bhf[0], bhf[1], sVh_u + roff + in2*16u);
                ldsm_x2_trans(blf[0], blf[1], sVl_u + roff + in2*16u);
                mma16816(acc[in2], ah, bhf);
                mma16816(acc[in2], ah, blf);
                mma16816(acc[in2], al, bhf);
            }
        }
    }

    // epilogue: normalize, write head-interleaved [B,S,D]
    const float inv0 = 1.f / l0;
    const float inv1 = 1.f / l1;
    const int r0 = q0 + wid*16 + grp;
    const int r1 = r0 + 8;
    #pragma unroll
    for (int in2 = 0; in2 < 8; in2++) {
        const int dc = h*HDIM + in2*8 + qid*2;
        float2 y0 = make_float2(acc[in2][0]*inv0, acc[in2][1]*inv0);
        float2 y1 = make_float2(acc[in2][2]*inv1, acc[in2][3]*inv1);
        *reinterpret_cast<float2*>(&g_X[((size_t)b*SEQ + r0)*D_MODEL + dc]) = y0;
        *reinterpret_cast<float2*>(&g_X[((size_t)b*SEQ + r1)*D_MODEL + dc]) = y1;
    }
}

// ---------------------------------------------------------------------------
extern "C" void kernel_launch(void* const* d_in, const int* in_sizes, int n_in,
                              void* d_out, int out_size)
{
    (void)in_sizes; (void)n_in; (void)out_size;
    const float* q  = (const float*)d_in[0];
    const float* k  = (const float*)d_in[1];
    const float* v  = (const float*)d_in[2];
    const float* Wq = (const float*)d_in[3];
    const float* bq = (const float*)d_in[4];
    const float* Wk = (const float*)d_in[5];
    const float* bk = (const float*)d_in[6];
    const float* Wv = (const float*)d_in[7];
    const float* bv = (const float*)d_in[8];
    const float* Wo = (const float*)d_in[9];
    const float* bo = (const float*)d_in[10];
    float* out = (float*)d_out;

    float *gq, *gk, *gv, *gx;
    cudaGetSymbolAddress((void**)&gq, g_Q);
    cudaGetSymbolAddress((void**)&gk, g_K);
    cudaGetSymbolAddress((void**)&gv, g_V);
    cudaGetSymbolAddress((void**)&gx, g_X);

    const dim3 gg(D_MODEL/128, NTOK/128);   // (8, 64)

    gemm_tc<0><<<gg, 256>>>(q, Wq, bq, gq);
    gemm_tc<0><<<gg, 256>>>(k, Wk, bk, gk);
    gemm_tc<0><<<gg, 256>>>(v, Wv, bv, gv);

    attn_mma<<<dim3(SEQ/128, BATCH*NHEAD), 256>>>();

    gemm_tc<1><<<gg, 256>>>(gx, Wo, bo, out);
}